// round 12
// baseline (speedup 1.0000x reference)
#include <cuda_runtime.h>
#include <cuda_fp16.h>
#include <cstdint>
#include <math.h>

#define NN 50000
#define EE 1600000
#define DD 256
#define GG 64

// ---------------- static device scratch ----------------
__device__ float4 g_act4[NN * DD / 4];        // final activation (fp32, pooling)
__device__ __half g_xsA[(NN + 128) * DD];     // ping-pong gather buffers
__device__ __half g_xsB[(NN + 128) * DD];
__device__ __half g_Wth[4 * DD * DD];         // per-layer W^T hi (fp16)  [n][k]
__device__ __half g_Wtl[4 * DD * DD];         // per-layer W^T lo residual (fp16)
__device__ float  g_dis[NN];
__device__ int    g_degi[NN];
__device__ int    g_total;
__device__ int    g_rowstart[NN];
__device__ int    g_rowend[NN];
__device__ int    g_cursor[NN];
__device__ int    g_csr[EE];
__device__ int    g_cnt[GG];
__device__ int    g_start[GG];
__device__ float  g_pool[GG * 2 * DD];
__device__ float  g_m1[GG * 512];
__device__ float  g_m2[GG * 256];

// ---------------- small helpers ----------------
__device__ __forceinline__ uint32_t smem_u32(const void* p) {
    uint32_t a;
    asm("{ .reg .u64 t; cvta.to.shared.u64 t, %1; cvt.u32.u64 %0, t; }"
        : "=r"(a) : "l"(p));
    return a;
}

__device__ __forceinline__ void cp16(uint32_t dst, const void* src) {
    asm volatile("cp.async.cg.shared.global [%0], [%1], 16;"
                 :: "r"(dst), "l"(src) : "memory");
}
#define CP_COMMIT() asm volatile("cp.async.commit_group;" ::: "memory")

#define LDMX4(r, addr)                                                      \
    asm volatile("ldmatrix.sync.aligned.m8n8.x4.shared.b16 "                \
        "{%0,%1,%2,%3}, [%4];"                                              \
        : "=r"((r)[0]), "=r"((r)[1]), "=r"((r)[2]), "=r"((r)[3])            \
        : "r"(addr))

#define MMA_FP16(d, a, b0, b1)                                              \
    asm volatile("mma.sync.aligned.m16n8k16.row.col.f32.f16.f16.f32 "      \
        "{%0,%1,%2,%3}, {%4,%5,%6,%7}, {%8,%9}, {%0,%1,%2,%3};"             \
        : "+f"((d)[0]), "+f"((d)[1]), "+f"((d)[2]), "+f"((d)[3])            \
        : "r"((a)[0]), "r"((a)[1]), "r"((a)[2]), "r"((a)[3]),               \
          "r"(b0), "r"(b1))

// ---------------- prep kernels ----------------
__global__ void deg_kernel(const int* __restrict__ ei, const int* __restrict__ bi,
                           int E, int n) {
    int e = blockIdx.x * blockDim.x + threadIdx.x;
    if (e == 0) g_total = 0;
    if (e < E) atomicAdd(&g_degi[ei[E + e]], 1);
    if (e < n) atomicAdd(&g_cnt[bi[e]], 1);
}

__global__ void alloc_kernel(int n) {
    int i = blockIdx.x * blockDim.x + threadIdx.x;
    if (i < n) {
        int d = g_degi[i];
        g_dis[i] = rsqrtf(1.0f + (float)d);
        int r = atomicAdd(&g_total, d);
        g_rowstart[i] = r;
        g_rowend[i]   = r + d;
        g_cursor[i]   = r;
    }
}

__global__ void fill_kernel(const int* __restrict__ ei, int E) {
    int e = blockIdx.x * blockDim.x + threadIdx.x;
    if (e < E) {
        int dst = ei[E + e];
        int p = atomicAdd(&g_cursor[dst], 1);
        g_csr[p] = ei[e];
    }
}

__global__ void gscan_kernel() {
    if (threadIdx.x == 0) {
        int s = 0;
        for (int g = 0; g < GG; g++) { g_start[g] = s; s += g_cnt[g]; }
    }
}

// ---------------- xs0 = fp16(dis * x), x is [N,128] fp32 ----------------
__global__ void conv_x0_kernel(const float* __restrict__ x, int n) {
    int i = blockIdx.x * blockDim.x + threadIdx.x;  // over n*64 half2
    if (i >= n * 64) return;
    int node = i >> 6;
    float d = g_dis[node];
    float2 a = reinterpret_cast<const float2*>(x)[i];
    reinterpret_cast<__half2*>(g_xsA)[i] = __floats2half2_rn(d * a.x, d * a.y);
}

// W [KD][256] -> transposed fp16 hi/lo splits at Wt[layer] [256][KD]
__global__ void conv_w_kernel(const float* __restrict__ W, int KD, int layer) {
    int i = blockIdx.x * blockDim.x + threadIdx.x;
    if (i >= KD * 256) return;
    int k = i >> 8;
    int n = i & 255;
    float w = W[i];
    __half h = __float2half_rn(w);
    size_t off = (size_t)layer * DD * DD + (size_t)n * KD + k;
    g_Wth[off] = h;
    g_Wtl[off] = __float2half_rn(w - __half2float(h));
}

// ---------------- fused aggregate + GEMM --------------------------------
// Per CTA: 64 nodes x full 256-N output.
//   pipeline over 16-k chunks:
//     gather(c+1): Y[node][chunk] = dis*(xin[node]+sum_src xin[src]) (fp16 smem)
//     MMA(c):      z += Y_chunk @ (Wh+Wl)_chunk
//   epilogue: act = tanh(z+b); xout = fp16(dis*act); LAST: act fp32.
// xin != xout (ping-pong) — avoids the cross-CTA RW race.
// smem: 3 W stages x 16KB + 2 Y bufs x 2KB = 53248 B.
#define WST   16384
#define YB0   49152
#define SM_FUSED (YB0 + 2 * 2048)

template<int KD, bool LAST>
__global__ void __launch_bounds__(256, 2) agg_gemm(const __half* __restrict__ xin,
                                                   __half* __restrict__ xout,
                                                   const __half* __restrict__ Wh,
                                                   const __half* __restrict__ Wl,
                                                   const float* __restrict__ bias,
                                                   int M) {
    extern __shared__ char smc[];
    const uint32_t sb = smem_u32(smc);
    constexpr int NCH  = KD / 16;
    constexpr int ROWB = KD * 2;

    const int t    = threadIdx.x;
    const int lane = t & 31;
    const int w    = t >> 5;
    const int wm   = w & 1;    // 2 warps in M (64 rows)
    const int wn   = w >> 1;   // 4 warps in N (256 cols)
    const int m0   = blockIdx.x * 64;

    // gather role: 4 threads per node, 8B quarter each
    const int nl = t >> 2;
    const int q  = t & 3;
    const int ng = m0 + nl;
    int gs = 0, ge = 0;
    float dn = 0.0f;
    if (ng < M) { gs = g_rowstart[ng]; ge = g_rowend[ng]; dn = g_dis[ng]; }
    const char* xs = (const char*)xin;
    const uint32_t yoff = nl * 32 + ((((uint32_t)q >> 1) ^ ((nl >> 2) & 1)) << 4)
                          + (q & 1) * 8;

    float acc[2][8][4];
#pragma unroll
    for (int mt = 0; mt < 2; mt++)
#pragma unroll
        for (int nt = 0; nt < 8; nt++)
#pragma unroll
            for (int p = 0; p < 4; p++) acc[mt][nt][p] = 0.0f;

    // stage W chunk c into buffer c%3: 2 arrays x 256 rows x 2 16B units
    auto stage = [&](int c) {
        uint32_t base = sb + (c % 3) * WST;
#pragma unroll
        for (int j = 0; j < 4; j++) {
            int idx = t + j * 256;      // 0..1023
            int arr = idx >> 9;         // 0=Wh 1=Wl
            int rem = idx & 511;
            int row = rem >> 1;
            int cc  = rem & 1;
            const __half* src = (arr ? Wl : Wh) + (size_t)row * KD + c * 16 + cc * 8;
            uint32_t dst = base + arr * 8192 + row * 32 +
                           ((cc ^ ((row >> 2) & 1)) << 4);
            cp16(dst, src);
        }
        CP_COMMIT();
    };

    // gather one 16-k chunk of this thread's (node, quarter) into ga[4] (fp32)
    auto gather = [&](int c, float* ga) {
        const char* base = xs + c * 32 + q * 8;
        uint2 sv = __ldg((const uint2*)(base + (size_t)ng * ROWB));
        float2 t0 = __half22float2(*(__half2*)&sv.x);
        float2 t1 = __half22float2(*(__half2*)&sv.y);
        ga[0] = t0.x; ga[1] = t0.y; ga[2] = t1.x; ga[3] = t1.y;
        int i = gs;
        for (; i + 4 <= ge; i += 4) {
            int s0 = __ldg(&g_csr[i]);
            int s1 = __ldg(&g_csr[i + 1]);
            int s2 = __ldg(&g_csr[i + 2]);
            int s3 = __ldg(&g_csr[i + 3]);
            uint2 v0 = __ldg((const uint2*)(base + (size_t)s0 * ROWB));
            uint2 v1 = __ldg((const uint2*)(base + (size_t)s1 * ROWB));
            uint2 v2 = __ldg((const uint2*)(base + (size_t)s2 * ROWB));
            uint2 v3 = __ldg((const uint2*)(base + (size_t)s3 * ROWB));
            float2 u;
            u = __half22float2(*(__half2*)&v0.x); ga[0] += u.x; ga[1] += u.y;
            u = __half22float2(*(__half2*)&v0.y); ga[2] += u.x; ga[3] += u.y;
            u = __half22float2(*(__half2*)&v1.x); ga[0] += u.x; ga[1] += u.y;
            u = __half22float2(*(__half2*)&v1.y); ga[2] += u.x; ga[3] += u.y;
            u = __half22float2(*(__half2*)&v2.x); ga[0] += u.x; ga[1] += u.y;
            u = __half22float2(*(__half2*)&v2.y); ga[2] += u.x; ga[3] += u.y;
            u = __half22float2(*(__half2*)&v3.x); ga[0] += u.x; ga[1] += u.y;
            u = __half22float2(*(__half2*)&v3.y); ga[2] += u.x; ga[3] += u.y;
        }
        for (; i < ge; i++) {
            int s0 = __ldg(&g_csr[i]);
            uint2 v = __ldg((const uint2*)(base + (size_t)s0 * ROWB));
            float2 u;
            u = __half22float2(*(__half2*)&v.x); ga[0] += u.x; ga[1] += u.y;
            u = __half22float2(*(__half2*)&v.y); ga[2] += u.x; ga[3] += u.y;
        }
    };

    auto ystore = [&](int b, const float* ga) {
        __half2 p0 = __floats2half2_rn(dn * ga[0], dn * ga[1]);
        __half2 p1 = __floats2half2_rn(dn * ga[2], dn * ga[3]);
        *reinterpret_cast<uint2*>(smc + YB0 + b * 2048 + yoff) =
            make_uint2(*reinterpret_cast<uint32_t*>(&p0),
                       *reinterpret_cast<uint32_t*>(&p1));
    };

    // prologue
    stage(0);
    stage(1);
    {
        float ga[4];
        gather(0, ga);
        ystore(0, ga);
    }

    const int lr  = lane & 7;
    const int grp = lane >> 3;
    float gnext[4];

    for (int c = 0; c < NCH; c++) {
        asm volatile("cp.async.wait_group 1;" ::: "memory");
        __syncthreads();   // Y buf[c&1] + W chunk c visible; prior readers done

        if (c + 1 < NCH) gather(c + 1, gnext);   // LDGs overlap MMA below

        uint32_t ysA = sb + YB0 + (c & 1) * 2048;
        uint32_t sBh = sb + (c % 3) * WST;
        uint32_t sBl = sBh + 8192;

        uint32_t af[2][4];
#pragma unroll
        for (int mt = 0; mt < 2; mt++) {
            int row = wm * 32 + mt * 16 + lr + ((grp & 1) << 3);
            int cc  = grp >> 1;
            uint32_t off = row * 32 + ((cc ^ ((row >> 2) & 1)) << 4);
            LDMX4(af[mt], ysA + off);
        }

        if (c + 2 < NCH) stage(c + 2);

#pragma unroll
        for (int ntp = 0; ntp < 4; ntp++) {
            int row = wn * 64 + ntp * 16 + lr + ((grp >> 1) << 3);
            int cc  = grp & 1;
            uint32_t off = row * 32 + ((cc ^ ((row >> 2) & 1)) << 4);
            uint32_t bh[4], bl[4];
            LDMX4(bh, sBh + off);
            LDMX4(bl, sBl + off);
#pragma unroll
            for (int mt = 0; mt < 2; mt++) {
                MMA_FP16(acc[mt][2 * ntp],     af[mt], bh[0], bh[1]);
                MMA_FP16(acc[mt][2 * ntp],     af[mt], bl[0], bl[1]);
                MMA_FP16(acc[mt][2 * ntp + 1], af[mt], bh[2], bh[3]);
                MMA_FP16(acc[mt][2 * ntp + 1], af[mt], bl[2], bl[3]);
            }
        }

        if (c + 1 < NCH) {
            __syncthreads();   // MMA readers done with buf (c+1)&1 before overwrite
            ystore((c + 1) & 1, gnext);
        }
    }

    // epilogue: act = tanh(z + b); xout = fp16(dis*act); LAST: act fp32
    float* actout = (float*)g_act4;
#pragma unroll
    for (int mt = 0; mt < 2; mt++) {
        int r0 = m0 + wm * 32 + mt * 16 + (lane >> 2);
        int r1 = r0 + 8;
        float d0 = (r0 < M) ? g_dis[r0] : 0.0f;
        float d1 = (r1 < M) ? g_dis[r1] : 0.0f;
#pragma unroll
        for (int nt = 0; nt < 8; nt++) {
            int nc = wn * 64 + nt * 8 + (lane & 3) * 2;
            float b0 = __ldg(&bias[nc]);
            float b1 = __ldg(&bias[nc + 1]);
            if (r0 < M) {
                float t0 = tanhf(acc[mt][nt][0] + b0);
                float t1 = tanhf(acc[mt][nt][1] + b1);
                if (LAST) {
                    *reinterpret_cast<float2*>(actout + (size_t)r0 * DD + nc) =
                        make_float2(t0, t1);
                } else {
                    *reinterpret_cast<__half2*>(xout + (size_t)r0 * DD + nc) =
                        __floats2half2_rn(d0 * t0, d0 * t1);
                }
            }
            if (r1 < M) {
                float t2 = tanhf(acc[mt][nt][2] + b0);
                float t3 = tanhf(acc[mt][nt][3] + b1);
                if (LAST) {
                    *reinterpret_cast<float2*>(actout + (size_t)r1 * DD + nc) =
                        make_float2(t2, t3);
                } else {
                    *reinterpret_cast<__half2*>(xout + (size_t)r1 * DD + nc) =
                        __floats2half2_rn(d1 * t2, d1 * t3);
                }
            }
        }
    }
}

// ---------------- per-graph max + mean pooling (64-feature strips) ----------
__global__ void pool_kernel() {
    int g  = blockIdx.x;
    int fc = blockIdx.y;
    int f  = fc * 64 + threadIdx.x;
    int s  = g_start[g];
    int c  = g_cnt[g];
    const float* act = (const float*)g_act4;
    float mx = -INFINITY, sm = 0.f;
    for (int r = 0; r < c; r++) {
        float v = act[(size_t)(s + r) * DD + f];
        mx = fmaxf(mx, v);
        sm += v;
    }
    g_pool[g * (2 * DD) + f]      = mx;
    g_pool[g * (2 * DD) + DD + f] = sm / fmaxf((float)c, 1.0f);
}

// ---------------- tiny MLP ----------------
template<bool RELU>
__global__ void mlp_kernel(const float* __restrict__ A, const float* __restrict__ W,
                           const float* __restrict__ bias, float* __restrict__ C,
                           int K, int Nc) {
    __shared__ float sA[512];
    int row = blockIdx.x;
    for (int k = threadIdx.x; k < K; k += blockDim.x) sA[k] = A[(size_t)row * K + k];
    __syncthreads();
    for (int n = threadIdx.x; n < Nc; n += blockDim.x) {
        float acc = bias[n];
        for (int k = 0; k < K; k++) acc = fmaf(sA[k], W[(size_t)k * Nc + n], acc);
        C[(size_t)row * Nc + n] = RELU ? fmaxf(acc, 0.f) : acc;
    }
}

// ---------------- launch ----------------
extern "C" void kernel_launch(void* const* d_in, const int* in_sizes, int n_in,
                              void* d_out, int out_size) {
    const float* x   = (const float*)d_in[0];
    const int*   ei  = (const int*)d_in[1];
    const int*   bi  = (const int*)d_in[2];
    const float* W0 = (const float*)d_in[3];  const float* b0 = (const float*)d_in[4];
    const float* W1 = (const float*)d_in[5];  const float* b1 = (const float*)d_in[6];
    const float* W2 = (const float*)d_in[7];  const float* b2 = (const float*)d_in[8];
    const float* W3 = (const float*)d_in[9];  const float* b3 = (const float*)d_in[10];
    const float* fc1w = (const float*)d_in[11]; const float* fc1b = (const float*)d_in[12];
    const float* fc2w = (const float*)d_in[13]; const float* fc2b = (const float*)d_in[14];
    const float* ow   = (const float*)d_in[15]; const float* ob   = (const float*)d_in[16];

    const int F = 128;
    int N = in_sizes[0] / F;
    int E = in_sizes[1] / 2;
    int NB = (N + 255) / 256;

    void *p_degi, *p_cnt, *p_pool, *p_m1, *p_m2, *p_wh, *p_wl, *p_xa, *p_xb;
    cudaGetSymbolAddress(&p_degi, g_degi);
    cudaGetSymbolAddress(&p_cnt,  g_cnt);
    cudaGetSymbolAddress(&p_pool, g_pool);
    cudaGetSymbolAddress(&p_m1,   g_m1);
    cudaGetSymbolAddress(&p_m2,   g_m2);
    cudaGetSymbolAddress(&p_wh,   g_Wth);
    cudaGetSymbolAddress(&p_wl,   g_Wtl);
    cudaGetSymbolAddress(&p_xa,   g_xsA);
    cudaGetSymbolAddress(&p_xb,   g_xsB);

    cudaFuncSetAttribute(agg_gemm<128, false>,
                         cudaFuncAttributeMaxDynamicSharedMemorySize, SM_FUSED);
    cudaFuncSetAttribute(agg_gemm<256, false>,
                         cudaFuncAttributeMaxDynamicSharedMemorySize, SM_FUSED);
    cudaFuncSetAttribute(agg_gemm<256, true>,
                         cudaFuncAttributeMaxDynamicSharedMemorySize, SM_FUSED);

    int fblocks = (N + 63) / 64;

    // prep
    cudaMemsetAsync(p_degi, 0, (size_t)N * sizeof(int), 0);
    cudaMemsetAsync(p_cnt, 0, GG * sizeof(int), 0);
    deg_kernel<<<(E + 255) / 256, 256>>>(ei, bi, E, N);
    alloc_kernel<<<NB, 256>>>(N);
    conv_x0_kernel<<<(N * 64 + 255) / 256, 256>>>(x, N);
    fill_kernel<<<(E + 255) / 256, 256>>>(ei, E);
    gscan_kernel<<<1, 32>>>();

    // all W splits upfront
    conv_w_kernel<<<(128 * 256 + 255) / 256, 256>>>(W0, 128, 0);
    conv_w_kernel<<<(256 * 256 + 255) / 256, 256>>>(W1, 256, 1);
    conv_w_kernel<<<(256 * 256 + 255) / 256, 256>>>(W2, 256, 2);
    conv_w_kernel<<<(256 * 256 + 255) / 256, 256>>>(W3, 256, 3);

    const __half* wh = (const __half*)p_wh;
    const __half* wl = (const __half*)p_wl;
    __half* xa = (__half*)p_xa;
    __half* xb = (__half*)p_xb;

    // ping-pong: A -> B -> A -> B -> act
    agg_gemm<128, false><<<fblocks, 256, SM_FUSED>>>(xa, xb, wh, wl, b0, N);
    agg_gemm<256, false><<<fblocks, 256, SM_FUSED>>>(xb, xa, wh + DD * DD, wl + DD * DD, b1, N);
    agg_gemm<256, false><<<fblocks, 256, SM_FUSED>>>(xa, xb, wh + 2 * DD * DD, wl + 2 * DD * DD, b2, N);
    agg_gemm<256, true ><<<fblocks, 256, SM_FUSED>>>(xb, xa, wh + 3 * DD * DD, wl + 3 * DD * DD, b3, N);

    // pooling + MLP
    pool_kernel<<<dim3(GG, 4), 64>>>();
    mlp_kernel<true ><<<GG, 256>>>((const float*)p_pool, fc1w, fc1b, (float*)p_m1, 2 * DD, 512);
    mlp_kernel<true ><<<GG, 256>>>((const float*)p_m1,   fc2w, fc2b, (float*)p_m2, 512, 256);
    mlp_kernel<false><<<GG, 32 >>>((const float*)p_m2,   ow,   ob,   (float*)d_out, 256, 10);
}

// round 13
// speedup vs baseline: 1.9402x; 1.9402x over previous
#include <cuda_runtime.h>
#include <cuda_fp16.h>
#include <cstdint>
#include <math.h>

#define NN 50000
#define EE 1600000
#define DD 256
#define GG 64

// ---------------- static device scratch ----------------
__device__ float4 g_act4[NN * DD / 4];        // final activation (fp32, pooling)
__device__ __half g_xs16[(NN + 128) * DD];    // xs = dis*act (fp16 gather array)
__device__ __half g_Y16[(NN + 128) * DD];     // Y = GEMM input (fp16)
__device__ __half g_Wth[4 * DD * DD];         // per-layer W^T hi (fp16)  [n][k]
__device__ __half g_Wtl[4 * DD * DD];         // per-layer W^T lo residual (fp16)
__device__ float  g_dis[NN];
__device__ int    g_degi[NN];
__device__ int    g_total;
__device__ int    g_rowstart[NN];
__device__ int    g_rowend[NN];
__device__ int    g_cursor[NN];
__device__ int    g_csr[EE];
__device__ int    g_cnt[GG];
__device__ int    g_start[GG];
__device__ float  g_pool[GG * 2 * DD];
__device__ float  g_m1[GG * 512];
__device__ float  g_m2[GG * 256];

// ---------------- small helpers ----------------
__device__ __forceinline__ uint32_t smem_u32(const void* p) {
    uint32_t a;
    asm("{ .reg .u64 t; cvta.to.shared.u64 t, %1; cvt.u32.u64 %0, t; }"
        : "=r"(a) : "l"(p));
    return a;
}

__device__ __forceinline__ void cp16(uint32_t dst, const void* src) {
    asm volatile("cp.async.cg.shared.global [%0], [%1], 16;"
                 :: "r"(dst), "l"(src) : "memory");
}
#define CP_COMMIT() asm volatile("cp.async.commit_group;" ::: "memory")

#define LDMX4(r, addr)                                                      \
    asm volatile("ldmatrix.sync.aligned.m8n8.x4.shared.b16 "                \
        "{%0,%1,%2,%3}, [%4];"                                              \
        : "=r"((r)[0]), "=r"((r)[1]), "=r"((r)[2]), "=r"((r)[3])            \
        : "r"(addr))

#define MMA_FP16(d, a, b0, b1)                                              \
    asm volatile("mma.sync.aligned.m16n8k16.row.col.f32.f16.f16.f32 "      \
        "{%0,%1,%2,%3}, {%4,%5,%6,%7}, {%8,%9}, {%0,%1,%2,%3};"             \
        : "+f"((d)[0]), "+f"((d)[1]), "+f"((d)[2]), "+f"((d)[3])            \
        : "r"((a)[0]), "r"((a)[1]), "r"((a)[2]), "r"((a)[3]),               \
          "r"(b0), "r"(b1))

// ---------------- prep kernels ----------------
// degree histogram + batch-count fused into one sweep
__global__ void deg_kernel(const int* __restrict__ ei, const int* __restrict__ bi,
                           int E, int n) {
    int e = blockIdx.x * blockDim.x + threadIdx.x;
    if (e == 0) g_total = 0;
    if (e < E) atomicAdd(&g_degi[ei[E + e]], 1);
    if (e < n) atomicAdd(&g_cnt[bi[e]], 1);
}

// dis + CSR range allocation (unordered rowstart via atomic; valid partition)
__global__ void alloc_kernel(int n) {
    int i = blockIdx.x * blockDim.x + threadIdx.x;
    if (i < n) {
        int d = g_degi[i];
        g_dis[i] = rsqrtf(1.0f + (float)d);
        int r = atomicAdd(&g_total, d);
        g_rowstart[i] = r;
        g_rowend[i]   = r + d;
        g_cursor[i]   = r;
    }
}

__global__ void fill_kernel(const int* __restrict__ ei, int E) {
    int e = blockIdx.x * blockDim.x + threadIdx.x;
    if (e < E) {
        int dst = ei[E + e];
        int p = atomicAdd(&g_cursor[dst], 1);
        g_csr[p] = ei[e];
    }
}

__global__ void gscan_kernel() {
    if (threadIdx.x == 0) {
        int s = 0;
        for (int g = 0; g < GG; g++) { g_start[g] = s; s += g_cnt[g]; }
    }
}

// ---------------- xs0 = fp16(dis * x), x is [N,128] fp32 ----------------
__global__ void conv_x0_kernel(const float* __restrict__ x, int n) {
    int i = blockIdx.x * blockDim.x + threadIdx.x;  // over n*64 half2
    if (i >= n * 64) return;
    int node = i >> 6;
    float d = g_dis[node];
    float2 a = reinterpret_cast<const float2*>(x)[i];
    reinterpret_cast<__half2*>(g_xs16)[i] = __floats2half2_rn(d * a.x, d * a.y);
}

// W [KD][256] -> transposed fp16 hi/lo splits at Wt[layer] [256][KD]
__global__ void conv_w_kernel(const float* __restrict__ W, int KD, int layer) {
    int i = blockIdx.x * blockDim.x + threadIdx.x;
    if (i >= KD * 256) return;
    int k = i >> 8;
    int n = i & 255;
    float w = W[i];
    __half h = __float2half_rn(w);
    size_t off = (size_t)layer * DD * DD + (size_t)n * KD + k;
    g_Wth[off] = h;
    g_Wtl[off] = __float2half_rn(w - __half2float(h));
}

// ---------------- CSR aggregate (fp16 gather, fp32 accum) --------------------
// Y[dst] = dis[dst] * (xs[dst] + sum_{src} xs[src]); write fp16 Y.
// 64 threads per node, 4 nodes per 256-thread block.
template<int KD>
__global__ void __launch_bounds__(256) aggregate_kernel(int n) {
    int node = blockIdx.x * 4 + (threadIdx.x >> 6);
    int f    = threadIdx.x & 63;
    if (node >= n) return;

    int s = g_rowstart[node];
    int e = g_rowend[node];
    const char* xs = (const char*)g_xs16;
    constexpr size_t ROWB = KD * 2;

    if constexpr (KD == 256) {
        uint2 sv = __ldg((const uint2*)(xs + (size_t)node * ROWB) + f);
        float2 a0 = __half22float2(*(__half2*)&sv.x);
        float2 a1 = __half22float2(*(__half2*)&sv.y);
        int i = s;
        for (; i + 4 <= e; i += 4) {
            int s0 = __ldg(&g_csr[i]);
            int s1 = __ldg(&g_csr[i + 1]);
            int s2 = __ldg(&g_csr[i + 2]);
            int s3 = __ldg(&g_csr[i + 3]);
            uint2 v0 = __ldg((const uint2*)(xs + (size_t)s0 * ROWB) + f);
            uint2 v1 = __ldg((const uint2*)(xs + (size_t)s1 * ROWB) + f);
            uint2 v2 = __ldg((const uint2*)(xs + (size_t)s2 * ROWB) + f);
            uint2 v3 = __ldg((const uint2*)(xs + (size_t)s3 * ROWB) + f);
            float2 t;
            t = __half22float2(*(__half2*)&v0.x); a0.x += t.x; a0.y += t.y;
            t = __half22float2(*(__half2*)&v0.y); a1.x += t.x; a1.y += t.y;
            t = __half22float2(*(__half2*)&v1.x); a0.x += t.x; a0.y += t.y;
            t = __half22float2(*(__half2*)&v1.y); a1.x += t.x; a1.y += t.y;
            t = __half22float2(*(__half2*)&v2.x); a0.x += t.x; a0.y += t.y;
            t = __half22float2(*(__half2*)&v2.y); a1.x += t.x; a1.y += t.y;
            t = __half22float2(*(__half2*)&v3.x); a0.x += t.x; a0.y += t.y;
            t = __half22float2(*(__half2*)&v3.y); a1.x += t.x; a1.y += t.y;
        }
        for (; i < e; i++) {
            int s0 = __ldg(&g_csr[i]);
            uint2 v = __ldg((const uint2*)(xs + (size_t)s0 * ROWB) + f);
            float2 t;
            t = __half22float2(*(__half2*)&v.x); a0.x += t.x; a0.y += t.y;
            t = __half22float2(*(__half2*)&v.y); a1.x += t.x; a1.y += t.y;
        }
        float d = g_dis[node];
        __half2 y0 = __floats2half2_rn(d * a0.x, d * a0.y);
        __half2 y1 = __floats2half2_rn(d * a1.x, d * a1.y);
        reinterpret_cast<uint2*>(g_Y16)[(size_t)node * 64 + f] =
            make_uint2(*reinterpret_cast<uint32_t*>(&y0),
                       *reinterpret_cast<uint32_t*>(&y1));
    } else {  // KD == 128
        uint32_t sv = __ldg((const uint32_t*)(xs + (size_t)node * ROWB) + f);
        float2 a0 = __half22float2(*(__half2*)&sv);
        int i = s;
        for (; i + 4 <= e; i += 4) {
            int s0 = __ldg(&g_csr[i]);
            int s1 = __ldg(&g_csr[i + 1]);
            int s2 = __ldg(&g_csr[i + 2]);
            int s3 = __ldg(&g_csr[i + 3]);
            uint32_t v0 = __ldg((const uint32_t*)(xs + (size_t)s0 * ROWB) + f);
            uint32_t v1 = __ldg((const uint32_t*)(xs + (size_t)s1 * ROWB) + f);
            uint32_t v2 = __ldg((const uint32_t*)(xs + (size_t)s2 * ROWB) + f);
            uint32_t v3 = __ldg((const uint32_t*)(xs + (size_t)s3 * ROWB) + f);
            float2 t;
            t = __half22float2(*(__half2*)&v0); a0.x += t.x; a0.y += t.y;
            t = __half22float2(*(__half2*)&v1); a0.x += t.x; a0.y += t.y;
            t = __half22float2(*(__half2*)&v2); a0.x += t.x; a0.y += t.y;
            t = __half22float2(*(__half2*)&v3); a0.x += t.x; a0.y += t.y;
        }
        for (; i < e; i++) {
            int s0 = __ldg(&g_csr[i]);
            uint32_t v = __ldg((const uint32_t*)(xs + (size_t)s0 * ROWB) + f);
            float2 t = __half22float2(*(__half2*)&v);
            a0.x += t.x; a0.y += t.y;
        }
        float d = g_dis[node];
        __half2 y = __floats2half2_rn(d * a0.x, d * a0.y);
        reinterpret_cast<uint32_t*>(g_Y16)[(size_t)node * 64 + f] =
            *reinterpret_cast<uint32_t*>(&y);
    }
}

// ---------------- fp16 2-product GEMM (mma.sync + ldmatrix + 3-stage cp.async)
// z = Y @ (Wh + Wl); act = tanh(z + b); xs16 = fp16(dis*act); LAST: act fp32.
#define ARRB 4096               // 128 rows * 32B
#define STGB (3 * ARRB)         // 12288 (Y, Wh, Wl)
#define SM_TOTAL (3 * STGB)     // 36864

template<int KD, bool LAST>
__global__ void __launch_bounds__(256) gemm_mma(const __half* __restrict__ Wh,
                                                const __half* __restrict__ Wl,
                                                const float* __restrict__ bias, int M) {
    extern __shared__ char smc[];
    const uint32_t sb = smem_u32(smc);
    const int t    = threadIdx.x;
    const int lane = t & 31;
    const int w    = t >> 5;
    const int wm   = w & 3;
    const int wn   = w >> 2;
    const int m0   = blockIdx.y * 128;
    const int n0   = blockIdx.x * 128;

    float acc[2][8][4];
#pragma unroll
    for (int mt = 0; mt < 2; mt++)
#pragma unroll
        for (int nt = 0; nt < 8; nt++)
#pragma unroll
            for (int q = 0; q < 4; q++) acc[mt][nt][q] = 0.0f;

    // stage one 16-k chunk: 3 arrays x 128 rows x 2 chunks = 768 x 16B; 3/thread
    auto stage = [&](int c, int buf) {
#pragma unroll
        for (int j = 0; j < 3; j++) {
            int idx = t + j * 256;
            int arr = idx >> 8;       // 0=Y 1=Wh 2=Wl
            int rem = idx & 255;
            int row = rem >> 1;
            int cc  = rem & 1;
            const __half* src;
            int gr;
            if (arr == 0)      { src = g_Y16; gr = m0 + row; }
            else if (arr == 1) { src = Wh;    gr = n0 + row; }
            else               { src = Wl;    gr = n0 + row; }
            src += (size_t)gr * KD + c * 16 + cc * 8;
            uint32_t dst = sb + buf * STGB + arr * ARRB + row * 32 +
                           ((cc ^ ((row >> 2) & 1)) << 4);
            cp16(dst, src);
        }
        CP_COMMIT();
    };

    stage(0, 0);
    stage(1, 1);

    const int NCH = KD / 16;
    const int lr  = lane & 7;
    const int grp = lane >> 3;

    for (int c = 0; c < NCH; c++) {
        asm volatile("cp.async.wait_group 1;" ::: "memory");
        __syncthreads();
        int buf = c % 3;
        uint32_t sA  = sb + buf * STGB;
        uint32_t sBh = sA + ARRB;
        uint32_t sBl = sA + 2 * ARRB;

        uint32_t af[2][4];
#pragma unroll
        for (int mt = 0; mt < 2; mt++) {
            int row = wm * 32 + mt * 16 + lr + ((grp & 1) << 3);
            int cc  = grp >> 1;
            uint32_t off = row * 32 + ((cc ^ ((row >> 2) & 1)) << 4);
            LDMX4(af[mt], sA + off);
        }

        if (c + 2 < NCH) stage(c + 2, (c + 2) % 3);

#pragma unroll
        for (int ntp = 0; ntp < 4; ntp++) {
            int row = wn * 64 + ntp * 16 + lr + ((grp >> 1) << 3);
            int cc  = grp & 1;
            uint32_t off = row * 32 + ((cc ^ ((row >> 2) & 1)) << 4);
            uint32_t bh[4], bl[4];
            LDMX4(bh, sBh + off);
            LDMX4(bl, sBl + off);
#pragma unroll
            for (int mt = 0; mt < 2; mt++) {
                MMA_FP16(acc[mt][2 * ntp],     af[mt], bh[0], bh[1]);
                MMA_FP16(acc[mt][2 * ntp],     af[mt], bl[0], bl[1]);
                MMA_FP16(acc[mt][2 * ntp + 1], af[mt], bh[2], bh[3]);
                MMA_FP16(acc[mt][2 * ntp + 1], af[mt], bl[2], bl[3]);
            }
        }
    }

    // epilogue
    float* actout = (float*)g_act4;
#pragma unroll
    for (int mt = 0; mt < 2; mt++) {
        int r0 = m0 + wm * 32 + mt * 16 + (lane >> 2);
        int r1 = r0 + 8;
        float d0 = (r0 < M) ? g_dis[r0] : 0.0f;
        float d1 = (r1 < M) ? g_dis[r1] : 0.0f;
#pragma unroll
        for (int nt = 0; nt < 8; nt++) {
            int nc = n0 + wn * 64 + nt * 8 + (lane & 3) * 2;
            float b0 = __ldg(&bias[nc]);
            float b1 = __ldg(&bias[nc + 1]);
            if (r0 < M) {
                float t0 = tanhf(acc[mt][nt][0] + b0);
                float t1 = tanhf(acc[mt][nt][1] + b1);
                if (LAST) {
                    *reinterpret_cast<float2*>(actout + (size_t)r0 * DD + nc) =
                        make_float2(t0, t1);
                } else {
                    *reinterpret_cast<__half2*>(g_xs16 + (size_t)r0 * DD + nc) =
                        __floats2half2_rn(d0 * t0, d0 * t1);
                }
            }
            if (r1 < M) {
                float t2 = tanhf(acc[mt][nt][2] + b0);
                float t3 = tanhf(acc[mt][nt][3] + b1);
                if (LAST) {
                    *reinterpret_cast<float2*>(actout + (size_t)r1 * DD + nc) =
                        make_float2(t2, t3);
                } else {
                    *reinterpret_cast<__half2*>(g_xs16 + (size_t)r1 * DD + nc) =
                        __floats2half2_rn(d1 * t2, d1 * t3);
                }
            }
        }
    }
}

// ---------------- per-graph max + mean pooling (64-feature strips) ----------
__global__ void pool_kernel() {
    int g  = blockIdx.x;
    int fc = blockIdx.y;                 // feature chunk 0..3
    int f  = fc * 64 + threadIdx.x;
    int s  = g_start[g];
    int c  = g_cnt[g];
    const float* act = (const float*)g_act4;
    float mx = -INFINITY, sm = 0.f;
    for (int r = 0; r < c; r++) {
        float v = act[(size_t)(s + r) * DD + f];
        mx = fmaxf(mx, v);
        sm += v;
    }
    g_pool[g * (2 * DD) + f]      = mx;
    g_pool[g * (2 * DD) + DD + f] = sm / fmaxf((float)c, 1.0f);
}

// ---------------- tiny MLP ----------------
template<bool RELU>
__global__ void mlp_kernel(const float* __restrict__ A, const float* __restrict__ W,
                           const float* __restrict__ bias, float* __restrict__ C,
                           int K, int Nc) {
    __shared__ float sA[512];
    int row = blockIdx.x;
    for (int k = threadIdx.x; k < K; k += blockDim.x) sA[k] = A[(size_t)row * K + k];
    __syncthreads();
    for (int n = threadIdx.x; n < Nc; n += blockDim.x) {
        float acc = bias[n];
        for (int k = 0; k < K; k++) acc = fmaf(sA[k], W[(size_t)k * Nc + n], acc);
        C[(size_t)row * Nc + n] = RELU ? fmaxf(acc, 0.f) : acc;
    }
}

// ---------------- launch ----------------
extern "C" void kernel_launch(void* const* d_in, const int* in_sizes, int n_in,
                              void* d_out, int out_size) {
    const float* x   = (const float*)d_in[0];
    const int*   ei  = (const int*)d_in[1];
    const int*   bi  = (const int*)d_in[2];
    const float* W0 = (const float*)d_in[3];  const float* b0 = (const float*)d_in[4];
    const float* W1 = (const float*)d_in[5];  const float* b1 = (const float*)d_in[6];
    const float* W2 = (const float*)d_in[7];  const float* b2 = (const float*)d_in[8];
    const float* W3 = (const float*)d_in[9];  const float* b3 = (const float*)d_in[10];
    const float* fc1w = (const float*)d_in[11]; const float* fc1b = (const float*)d_in[12];
    const float* fc2w = (const float*)d_in[13]; const float* fc2b = (const float*)d_in[14];
    const float* ow   = (const float*)d_in[15]; const float* ob   = (const float*)d_in[16];

    const int F = 128;
    int N = in_sizes[0] / F;
    int E = in_sizes[1] / 2;
    int NB = (N + 255) / 256;

    void *p_degi, *p_cnt, *p_pool, *p_m1, *p_m2, *p_wh, *p_wl;
    cudaGetSymbolAddress(&p_degi, g_degi);
    cudaGetSymbolAddress(&p_cnt,  g_cnt);
    cudaGetSymbolAddress(&p_pool, g_pool);
    cudaGetSymbolAddress(&p_m1,   g_m1);
    cudaGetSymbolAddress(&p_m2,   g_m2);
    cudaGetSymbolAddress(&p_wh,   g_Wth);
    cudaGetSymbolAddress(&p_wl,   g_Wtl);

    dim3 ggrid(2, (N + 127) / 128);
    int ablocks = (N + 3) / 4;

    // prep
    cudaMemsetAsync(p_degi, 0, (size_t)N * sizeof(int), 0);
    cudaMemsetAsync(p_cnt, 0, GG * sizeof(int), 0);
    deg_kernel<<<(E + 255) / 256, 256>>>(ei, bi, E, N);
    alloc_kernel<<<NB, 256>>>(N);
    conv_x0_kernel<<<(N * 64 + 255) / 256, 256>>>(x, N);
    fill_kernel<<<(E + 255) / 256, 256>>>(ei, E);
    gscan_kernel<<<1, 32>>>();

    aggregate_kernel<128><<<ablocks, 256>>>(N);

    // all W splits upfront
    conv_w_kernel<<<(128 * 256 + 255) / 256, 256>>>(W0, 128, 0);
    conv_w_kernel<<<(256 * 256 + 255) / 256, 256>>>(W1, 256, 1);
    conv_w_kernel<<<(256 * 256 + 255) / 256, 256>>>(W2, 256, 2);
    conv_w_kernel<<<(256 * 256 + 255) / 256, 256>>>(W3, 256, 3);

    const __half* wh = (const __half*)p_wh;
    const __half* wl = (const __half*)p_wl;

    gemm_mma<128, false><<<ggrid, 256, SM_TOTAL>>>(wh, wl, b0, N);

    aggregate_kernel<256><<<ablocks, 256>>>(N);
    gemm_mma<256, false><<<ggrid, 256, SM_TOTAL>>>(wh + DD * DD, wl + DD * DD, b1, N);

    aggregate_kernel<256><<<ablocks, 256>>>(N);
    gemm_mma<256, false><<<ggrid, 256, SM_TOTAL>>>(wh + 2 * DD * DD, wl + 2 * DD * DD, b2, N);

    aggregate_kernel<256><<<ablocks, 256>>>(N);
    gemm_mma<256, true><<<ggrid, 256, SM_TOTAL>>>(wh + 3 * DD * DD, wl + 3 * DD * DD, b3, N);

    // pooling + MLP
    pool_kernel<<<dim3(GG, 4), 64>>>();
    mlp_kernel<true ><<<GG, 256>>>((const float*)p_pool, fc1w, fc1b, (float*)p_m1, 2 * DD, 512);
    mlp_kernel<true ><<<GG, 256>>>((const float*)p_m1,   fc2w, fc2b, (float*)p_m2, 512, 256);
    mlp_kernel<false><<<GG, 32 >>>((const float*)p_m2,   ow,   ob,   (float*)d_out, 256, 10);
}

// round 14
// speedup vs baseline: 2.0784x; 1.0712x over previous
#include <cuda_runtime.h>
#include <cuda_fp16.h>
#include <cstdint>
#include <math.h>

#define NN 50000
#define EE 1600000
#define DD 256
#define GG 64

// ---------------- static device scratch ----------------
__device__ float4 g_act4[NN * DD / 4];        // final activation (fp32, pooling)
__device__ __half g_xs16[(NN + 128) * DD];    // xs = dis*act (fp16 gather array)
__device__ __half g_Y16[(NN + 128) * DD];     // Y = GEMM input (fp16)
__device__ __half g_Wth[4 * DD * DD];         // per-layer W^T hi (fp16)  [n][k]
__device__ __half g_Wtl[4 * DD * DD];         // per-layer W^T lo residual (fp16)
__device__ float  g_dis[NN];
__device__ int    g_degi[NN];
__device__ int    g_total;
__device__ int    g_rowstart[NN];
__device__ int    g_rowend[NN];
__device__ int    g_cursor[NN];
__device__ int    g_csr[EE];
__device__ int    g_cnt[GG];
__device__ int    g_start[GG];
__device__ float  g_pool[GG * 2 * DD];
__device__ float  g_m1[GG * 512];
__device__ float  g_m2[GG * 256];

// ---------------- small helpers ----------------
__device__ __forceinline__ uint32_t smem_u32(const void* p) {
    uint32_t a;
    asm("{ .reg .u64 t; cvta.to.shared.u64 t, %1; cvt.u32.u64 %0, t; }"
        : "=r"(a) : "l"(p));
    return a;
}

__device__ __forceinline__ void cp16(uint32_t dst, const void* src) {
    asm volatile("cp.async.cg.shared.global [%0], [%1], 16;"
                 :: "r"(dst), "l"(src) : "memory");
}
#define CP_COMMIT() asm volatile("cp.async.commit_group;" ::: "memory")

#define LDMX4(r, addr)                                                      \
    asm volatile("ldmatrix.sync.aligned.m8n8.x4.shared.b16 "                \
        "{%0,%1,%2,%3}, [%4];"                                              \
        : "=r"((r)[0]), "=r"((r)[1]), "=r"((r)[2]), "=r"((r)[3])            \
        : "r"(addr))

#define MMA_FP16(d, a, b0, b1)                                              \
    asm volatile("mma.sync.aligned.m16n8k16.row.col.f32.f16.f16.f32 "      \
        "{%0,%1,%2,%3}, {%4,%5,%6,%7}, {%8,%9}, {%0,%1,%2,%3};"             \
        : "+f"((d)[0]), "+f"((d)[1]), "+f"((d)[2]), "+f"((d)[3])            \
        : "r"((a)[0]), "r"((a)[1]), "r"((a)[2]), "r"((a)[3]),               \
          "r"(b0), "r"(b1))

// ---------------- prep kernels ----------------
// degree histogram + batch-count fused into one sweep
__global__ void deg_kernel(const int* __restrict__ ei, const int* __restrict__ bi,
                           int E, int n) {
    int e = blockIdx.x * blockDim.x + threadIdx.x;
    if (e == 0) g_total = 0;
    if (e < E) atomicAdd(&g_degi[ei[E + e]], 1);
    if (e < n) atomicAdd(&g_cnt[bi[e]], 1);
}

// dis + CSR range allocation + (block0) group-offset scan
__global__ void alloc_kernel(int n) {
    int i = blockIdx.x * blockDim.x + threadIdx.x;
    if (i < n) {
        int d = g_degi[i];
        g_dis[i] = rsqrtf(1.0f + (float)d);
        int r = atomicAdd(&g_total, d);
        g_rowstart[i] = r;
        g_rowend[i]   = r + d;
        g_cursor[i]   = r;
    }
    if (i == 0) {
        int s = 0;
        for (int g = 0; g < GG; g++) { g_start[g] = s; s += g_cnt[g]; }
    }
}

__global__ void fill_kernel(const int* __restrict__ ei, int E) {
    int e = blockIdx.x * blockDim.x + threadIdx.x;
    if (e < E) {
        int dst = ei[E + e];
        int p = atomicAdd(&g_cursor[dst], 1);
        g_csr[p] = ei[e];
    }
}

// ---------------- xs0 = fp16(dis * x), x is [N,128] fp32 ----------------
__global__ void conv_x0_kernel(const float* __restrict__ x, int n) {
    int i = blockIdx.x * blockDim.x + threadIdx.x;  // over n*64 half2
    if (i >= n * 64) return;
    int node = i >> 6;
    float d = g_dis[node];
    float2 a = reinterpret_cast<const float2*>(x)[i];
    reinterpret_cast<__half2*>(g_xs16)[i] = __floats2half2_rn(d * a.x, d * a.y);
}

// All 4 W's -> transposed fp16 hi/lo splits, one launch.
// i < 32768: layer0 (KD=128); else layers 1-3 (KD=256).
__global__ void conv_w_all(const float* __restrict__ W0, const float* __restrict__ W1,
                           const float* __restrict__ W2, const float* __restrict__ W3) {
    int i = blockIdx.x * blockDim.x + threadIdx.x;
    if (i >= 32768 + 3 * 65536) return;
    const float* W;
    int layer, KD, idx;
    if (i < 32768) { W = W0; layer = 0; KD = 128; idx = i; }
    else {
        int j = i - 32768;
        layer = 1 + j / 65536;
        idx = j % 65536;
        W = (layer == 1) ? W1 : (layer == 2 ? W2 : W3);
        KD = 256;
    }
    int k = idx >> 8;
    int n = idx & 255;
    float w = W[idx];
    __half h = __float2half_rn(w);
    size_t off = (size_t)layer * DD * DD + (size_t)n * KD + k;
    g_Wth[off] = h;
    g_Wtl[off] = __float2half_rn(w - __half2float(h));
}

// ---------------- CSR aggregate (fp16 gather, fp32 accum) --------------------
// Y[dst] = dis[dst] * (xs[dst] + sum_{src} xs[src]); write fp16 Y.
// 64 threads per node, 4 nodes per 256-thread block.
template<int KD>
__global__ void __launch_bounds__(256) aggregate_kernel(int n) {
    int node = blockIdx.x * 4 + (threadIdx.x >> 6);
    int f    = threadIdx.x & 63;
    if (node >= n) return;

    int s = g_rowstart[node];
    int e = g_rowend[node];
    const char* xs = (const char*)g_xs16;
    constexpr size_t ROWB = KD * 2;

    if constexpr (KD == 256) {
        uint2 sv = __ldg((const uint2*)(xs + (size_t)node * ROWB) + f);
        float2 a0 = __half22float2(*(__half2*)&sv.x);
        float2 a1 = __half22float2(*(__half2*)&sv.y);
        int i = s;
        for (; i + 4 <= e; i += 4) {
            int s0 = __ldg(&g_csr[i]);
            int s1 = __ldg(&g_csr[i + 1]);
            int s2 = __ldg(&g_csr[i + 2]);
            int s3 = __ldg(&g_csr[i + 3]);
            uint2 v0 = __ldg((const uint2*)(xs + (size_t)s0 * ROWB) + f);
            uint2 v1 = __ldg((const uint2*)(xs + (size_t)s1 * ROWB) + f);
            uint2 v2 = __ldg((const uint2*)(xs + (size_t)s2 * ROWB) + f);
            uint2 v3 = __ldg((const uint2*)(xs + (size_t)s3 * ROWB) + f);
            float2 t;
            t = __half22float2(*(__half2*)&v0.x); a0.x += t.x; a0.y += t.y;
            t = __half22float2(*(__half2*)&v0.y); a1.x += t.x; a1.y += t.y;
            t = __half22float2(*(__half2*)&v1.x); a0.x += t.x; a0.y += t.y;
            t = __half22float2(*(__half2*)&v1.y); a1.x += t.x; a1.y += t.y;
            t = __half22float2(*(__half2*)&v2.x); a0.x += t.x; a0.y += t.y;
            t = __half22float2(*(__half2*)&v2.y); a1.x += t.x; a1.y += t.y;
            t = __half22float2(*(__half2*)&v3.x); a0.x += t.x; a0.y += t.y;
            t = __half22float2(*(__half2*)&v3.y); a1.x += t.x; a1.y += t.y;
        }
        for (; i < e; i++) {
            int s0 = __ldg(&g_csr[i]);
            uint2 v = __ldg((const uint2*)(xs + (size_t)s0 * ROWB) + f);
            float2 t;
            t = __half22float2(*(__half2*)&v.x); a0.x += t.x; a0.y += t.y;
            t = __half22float2(*(__half2*)&v.y); a1.x += t.x; a1.y += t.y;
        }
        float d = g_dis[node];
        __half2 y0 = __floats2half2_rn(d * a0.x, d * a0.y);
        __half2 y1 = __floats2half2_rn(d * a1.x, d * a1.y);
        reinterpret_cast<uint2*>(g_Y16)[(size_t)node * 64 + f] =
            make_uint2(*reinterpret_cast<uint32_t*>(&y0),
                       *reinterpret_cast<uint32_t*>(&y1));
    } else {  // KD == 128
        uint32_t sv = __ldg((const uint32_t*)(xs + (size_t)node * ROWB) + f);
        float2 a0 = __half22float2(*(__half2*)&sv);
        int i = s;
        for (; i + 4 <= e; i += 4) {
            int s0 = __ldg(&g_csr[i]);
            int s1 = __ldg(&g_csr[i + 1]);
            int s2 = __ldg(&g_csr[i + 2]);
            int s3 = __ldg(&g_csr[i + 3]);
            uint32_t v0 = __ldg((const uint32_t*)(xs + (size_t)s0 * ROWB) + f);
            uint32_t v1 = __ldg((const uint32_t*)(xs + (size_t)s1 * ROWB) + f);
            uint32_t v2 = __ldg((const uint32_t*)(xs + (size_t)s2 * ROWB) + f);
            uint32_t v3 = __ldg((const uint32_t*)(xs + (size_t)s3 * ROWB) + f);
            float2 t;
            t = __half22float2(*(__half2*)&v0); a0.x += t.x; a0.y += t.y;
            t = __half22float2(*(__half2*)&v1); a0.x += t.x; a0.y += t.y;
            t = __half22float2(*(__half2*)&v2); a0.x += t.x; a0.y += t.y;
            t = __half22float2(*(__half2*)&v3); a0.x += t.x; a0.y += t.y;
        }
        for (; i < e; i++) {
            int s0 = __ldg(&g_csr[i]);
            uint32_t v = __ldg((const uint32_t*)(xs + (size_t)s0 * ROWB) + f);
            float2 t = __half22float2(*(__half2*)&v);
            a0.x += t.x; a0.y += t.y;
        }
        float d = g_dis[node];
        __half2 y = __floats2half2_rn(d * a0.x, d * a0.y);
        reinterpret_cast<uint32_t*>(g_Y16)[(size_t)node * 64 + f] =
            *reinterpret_cast<uint32_t*>(&y);
    }
}

// ---------------- fp16 2-product GEMM (mma.sync + ldmatrix + 3-stage cp.async)
// z = Y @ (Wh + Wl); act = tanh(z + b); xs16 = fp16(dis*act); LAST: act fp32.
#define ARRB 4096               // 128 rows * 32B
#define STGB (3 * ARRB)         // 12288 (Y, Wh, Wl)
#define SM_TOTAL (3 * STGB)     // 36864

template<int KD, bool LAST>
__global__ void __launch_bounds__(256, 2) gemm_mma(const __half* __restrict__ Wh,
                                                   const __half* __restrict__ Wl,
                                                   const float* __restrict__ bias,
                                                   int M) {
    extern __shared__ char smc[];
    const uint32_t sb = smem_u32(smc);
    const int t    = threadIdx.x;
    const int lane = t & 31;
    const int w    = t >> 5;
    const int wm   = w & 3;
    const int wn   = w >> 2;
    const int m0   = blockIdx.y * 128;
    const int n0   = blockIdx.x * 128;

    float acc[2][8][4];
#pragma unroll
    for (int mt = 0; mt < 2; mt++)
#pragma unroll
        for (int nt = 0; nt < 8; nt++)
#pragma unroll
            for (int q = 0; q < 4; q++) acc[mt][nt][q] = 0.0f;

    // stage one 16-k chunk: 3 arrays x 128 rows x 2 chunks = 768 x 16B; 3/thread
    auto stage = [&](int c, int buf) {
#pragma unroll
        for (int j = 0; j < 3; j++) {
            int idx = t + j * 256;
            int arr = idx >> 8;       // 0=Y 1=Wh 2=Wl
            int rem = idx & 255;
            int row = rem >> 1;
            int cc  = rem & 1;
            const __half* src;
            int gr;
            if (arr == 0)      { src = g_Y16; gr = m0 + row; }
            else if (arr == 1) { src = Wh;    gr = n0 + row; }
            else               { src = Wl;    gr = n0 + row; }
            src += (size_t)gr * KD + c * 16 + cc * 8;
            uint32_t dst = sb + buf * STGB + arr * ARRB + row * 32 +
                           ((cc ^ ((row >> 2) & 1)) << 4);
            cp16(dst, src);
        }
        CP_COMMIT();
    };

    stage(0, 0);
    stage(1, 1);

    const int NCH = KD / 16;
    const int lr  = lane & 7;
    const int grp = lane >> 3;

    for (int c = 0; c < NCH; c++) {
        asm volatile("cp.async.wait_group 1;" ::: "memory");
        __syncthreads();
        int buf = c % 3;
        uint32_t sA  = sb + buf * STGB;
        uint32_t sBh = sA + ARRB;
        uint32_t sBl = sA + 2 * ARRB;

        uint32_t af[2][4];
#pragma unroll
        for (int mt = 0; mt < 2; mt++) {
            int row = wm * 32 + mt * 16 + lr + ((grp & 1) << 3);
            int cc  = grp >> 1;
            uint32_t off = row * 32 + ((cc ^ ((row >> 2) & 1)) << 4);
            LDMX4(af[mt], sA + off);
        }

        if (c + 2 < NCH) stage(c + 2, (c + 2) % 3);

#pragma unroll
        for (int ntp = 0; ntp < 4; ntp++) {
            int row = wn * 64 + ntp * 16 + lr + ((grp >> 1) << 3);
            int cc  = grp & 1;
            uint32_t off = row * 32 + ((cc ^ ((row >> 2) & 1)) << 4);
            uint32_t bh[4], bl[4];
            LDMX4(bh, sBh + off);
            LDMX4(bl, sBl + off);
#pragma unroll
            for (int mt = 0; mt < 2; mt++) {
                MMA_FP16(acc[mt][2 * ntp],     af[mt], bh[0], bh[1]);
                MMA_FP16(acc[mt][2 * ntp],     af[mt], bl[0], bl[1]);
                MMA_FP16(acc[mt][2 * ntp + 1], af[mt], bh[2], bh[3]);
                MMA_FP16(acc[mt][2 * ntp + 1], af[mt], bl[2], bl[3]);
            }
        }
    }

    // epilogue
    float* actout = (float*)g_act4;
#pragma unroll
    for (int mt = 0; mt < 2; mt++) {
        int r0 = m0 + wm * 32 + mt * 16 + (lane >> 2);
        int r1 = r0 + 8;
        float d0 = (r0 < M) ? g_dis[r0] : 0.0f;
        float d1 = (r1 < M) ? g_dis[r1] : 0.0f;
#pragma unroll
        for (int nt = 0; nt < 8; nt++) {
            int nc = n0 + wn * 64 + nt * 8 + (lane & 3) * 2;
            float b0 = __ldg(&bias[nc]);
            float b1 = __ldg(&bias[nc + 1]);
            if (r0 < M) {
                float t0 = tanhf(acc[mt][nt][0] + b0);
                float t1 = tanhf(acc[mt][nt][1] + b1);
                if (LAST) {
                    *reinterpret_cast<float2*>(actout + (size_t)r0 * DD + nc) =
                        make_float2(t0, t1);
                } else {
                    *reinterpret_cast<__half2*>(g_xs16 + (size_t)r0 * DD + nc) =
                        __floats2half2_rn(d0 * t0, d0 * t1);
                }
            }
            if (r1 < M) {
                float t2 = tanhf(acc[mt][nt][2] + b0);
                float t3 = tanhf(acc[mt][nt][3] + b1);
                if (LAST) {
                    *reinterpret_cast<float2*>(actout + (size_t)r1 * DD + nc) =
                        make_float2(t2, t3);
                } else {
                    *reinterpret_cast<__half2*>(g_xs16 + (size_t)r1 * DD + nc) =
                        __floats2half2_rn(d1 * t2, d1 * t3);
                }
            }
        }
    }
}

// ---------------- per-graph max + mean pooling (64-feature strips) ----------
__global__ void pool_kernel() {
    int g  = blockIdx.x;
    int fc = blockIdx.y;                 // feature chunk 0..3
    int f  = fc * 64 + threadIdx.x;
    int s  = g_start[g];
    int c  = g_cnt[g];
    const float* act = (const float*)g_act4;
    float mx = -INFINITY, sm = 0.f;
    for (int r = 0; r < c; r++) {
        float v = act[(size_t)(s + r) * DD + f];
        mx = fmaxf(mx, v);
        sm += v;
    }
    g_pool[g * (2 * DD) + f]      = mx;
    g_pool[g * (2 * DD) + DD + f] = sm / fmaxf((float)c, 1.0f);
}

// ---------------- tiny MLP ----------------
template<bool RELU>
__global__ void mlp_kernel(const float* __restrict__ A, const float* __restrict__ W,
                           const float* __restrict__ bias, float* __restrict__ C,
                           int K, int Nc) {
    __shared__ float sA[512];
    int row = blockIdx.x;
    for (int k = threadIdx.x; k < K; k += blockDim.x) sA[k] = A[(size_t)row * K + k];
    __syncthreads();
    for (int n = threadIdx.x; n < Nc; n += blockDim.x) {
        float acc = bias[n];
        for (int k = 0; k < K; k++) acc = fmaf(sA[k], W[(size_t)k * Nc + n], acc);
        C[(size_t)row * Nc + n] = RELU ? fmaxf(acc, 0.f) : acc;
    }
}

// ---------------- launch ----------------
extern "C" void kernel_launch(void* const* d_in, const int* in_sizes, int n_in,
                              void* d_out, int out_size) {
    const float* x   = (const float*)d_in[0];
    const int*   ei  = (const int*)d_in[1];
    const int*   bi  = (const int*)d_in[2];
    const float* W0 = (const float*)d_in[3];  const float* b0 = (const float*)d_in[4];
    const float* W1 = (const float*)d_in[5];  const float* b1 = (const float*)d_in[6];
    const float* W2 = (const float*)d_in[7];  const float* b2 = (const float*)d_in[8];
    const float* W3 = (const float*)d_in[9];  const float* b3 = (const float*)d_in[10];
    const float* fc1w = (const float*)d_in[11]; const float* fc1b = (const float*)d_in[12];
    const float* fc2w = (const float*)d_in[13]; const float* fc2b = (const float*)d_in[14];
    const float* ow   = (const float*)d_in[15]; const float* ob   = (const float*)d_in[16];

    const int F = 128;
    int N = in_sizes[0] / F;
    int E = in_sizes[1] / 2;
    int NB = (N + 255) / 256;

    void *p_degi, *p_cnt, *p_pool, *p_m1, *p_m2, *p_wh, *p_wl;
    cudaGetSymbolAddress(&p_degi, g_degi);
    cudaGetSymbolAddress(&p_cnt,  g_cnt);
    cudaGetSymbolAddress(&p_pool, g_pool);
    cudaGetSymbolAddress(&p_m1,   g_m1);
    cudaGetSymbolAddress(&p_m2,   g_m2);
    cudaGetSymbolAddress(&p_wh,   g_Wth);
    cudaGetSymbolAddress(&p_wl,   g_Wtl);

    dim3 ggrid(2, (N + 127) / 128);
    int ablocks = (N + 3) / 4;

    // prep
    cudaMemsetAsync(p_degi, 0, (size_t)N * sizeof(int), 0);
    cudaMemsetAsync(p_cnt, 0, GG * sizeof(int), 0);
    deg_kernel<<<(E + 255) / 256, 256>>>(ei, bi, E, N);
    alloc_kernel<<<NB, 256>>>(N);
    conv_x0_kernel<<<(N * 64 + 255) / 256, 256>>>(x, N);
    fill_kernel<<<(E + 255) / 256, 256>>>(ei, E);

    // all W splits in one launch
    conv_w_all<<<(32768 + 3 * 65536 + 255) / 256, 256>>>(W0, W1, W2, W3);

    const __half* wh = (const __half*)p_wh;
    const __half* wl = (const __half*)p_wl;

    aggregate_kernel<128><<<ablocks, 256>>>(N);
    gemm_mma<128, false><<<ggrid, 256, SM_TOTAL>>>(wh, wl, b0, N);

    aggregate_kernel<256><<<ablocks, 256>>>(N);
    gemm_mma<256, false><<<ggrid, 256, SM_TOTAL>>>(wh + DD * DD, wl + DD * DD, b1, N);

    aggregate_kernel<256><<<ablocks, 256>>>(N);
    gemm_mma<256, false><<<ggrid, 256, SM_TOTAL>>>(wh + 2 * DD * DD, wl + 2 * DD * DD, b2, N);

    aggregate_kernel<256><<<ablocks, 256>>>(N);
    gemm_mma<256, true><<<ggrid, 256, SM_TOTAL>>>(wh + 3 * DD * DD, wl + 3 * DD * DD, b3, N);

    // pooling + MLP
    pool_kernel<<<dim3(GG, 4), 64>>>();
    mlp_kernel<true ><<<GG, 256>>>((const float*)p_pool, fc1w, fc1b, (float*)p_m1, 2 * DD, 512);
    mlp_kernel<true ><<<GG, 256>>>((const float*)p_m1,   fc2w, fc2b, (float*)p_m2, 512, 256);
    mlp_kernel<false><<<GG, 32 >>>((const float*)p_m2,   ow,   ob,   (float*)d_out, 256, 10);
}

// round 15
// speedup vs baseline: 2.3908x; 1.1503x over previous
#include <cuda_runtime.h>
#include <cuda_fp16.h>
#include <cstdint>
#include <math.h>

#define NN 50000
#define EE 1600000
#define DD 256
#define GG 64

// ---------------- static device scratch ----------------
__device__ float4 g_act4[NN * DD / 4];        // final activation (fp32, pooling)
__device__ __half g_xs16[(NN + 128) * DD];    // xs = dis*act (fp16 gather array)
__device__ __half g_Y16[(NN + 128) * DD];     // Y = GEMM input (fp16)
__device__ __half g_Wth[4 * DD * DD];         // per-layer W^T hi (fp16)  [n][k]
__device__ __half g_Wtl[4 * DD * DD];         // per-layer W^T lo residual (fp16)
__device__ float  g_dis[NN];
__device__ int    g_ints[NN + GG];            // [0,NN): degree  [NN,NN+GG): batch cnt
__device__ int    g_total;
__device__ int    g_rowstart[NN];
__device__ int    g_rowend[NN];
__device__ int    g_cursor[NN];
__device__ int    g_csr[EE];
__device__ int    g_start[GG];
__device__ float  g_pool[GG * 2 * DD];

// ---------------- small helpers ----------------
__device__ __forceinline__ uint32_t smem_u32(const void* p) {
    uint32_t a;
    asm("{ .reg .u64 t; cvta.to.shared.u64 t, %1; cvt.u32.u64 %0, t; }"
        : "=r"(a) : "l"(p));
    return a;
}

__device__ __forceinline__ void cp16(uint32_t dst, const void* src) {
    asm volatile("cp.async.cg.shared.global [%0], [%1], 16;"
                 :: "r"(dst), "l"(src) : "memory");
}
#define CP_COMMIT() asm volatile("cp.async.commit_group;" ::: "memory")

#define LDMX4(r, addr)                                                      \
    asm volatile("ldmatrix.sync.aligned.m8n8.x4.shared.b16 "                \
        "{%0,%1,%2,%3}, [%4];"                                              \
        : "=r"((r)[0]), "=r"((r)[1]), "=r"((r)[2]), "=r"((r)[3])            \
        : "r"(addr))

#define MMA_FP16(d, a, b0, b1)                                              \
    asm volatile("mma.sync.aligned.m16n8k16.row.col.f32.f16.f16.f32 "      \
        "{%0,%1,%2,%3}, {%4,%5,%6,%7}, {%8,%9}, {%0,%1,%2,%3};"             \
        : "+f"((d)[0]), "+f"((d)[1]), "+f"((d)[2]), "+f"((d)[3])            \
        : "r"((a)[0]), "r"((a)[1]), "r"((a)[2]), "r"((a)[3]),               \
          "r"(b0), "r"(b1))

// ---------------- prep kernels ----------------
// degree histogram + batch-count fused into one sweep
__global__ void deg_kernel(const int* __restrict__ ei, const int* __restrict__ bi,
                           int E, int n) {
    int e = blockIdx.x * blockDim.x + threadIdx.x;
    if (e == 0) g_total = 0;
    if (e < E) atomicAdd(&g_ints[ei[E + e]], 1);
    if (e < n) atomicAdd(&g_ints[NN + bi[e]], 1);
}

// dis + CSR range allocation + (thread0) group-offset scan
__global__ void alloc_kernel(int n) {
    int i = blockIdx.x * blockDim.x + threadIdx.x;
    if (i < n) {
        int d = g_ints[i];
        g_dis[i] = rsqrtf(1.0f + (float)d);
        int r = atomicAdd(&g_total, d);
        g_rowstart[i] = r;
        g_rowend[i]   = r + d;
        g_cursor[i]   = r;
    }
    if (i == 0) {
        int s = 0;
        for (int g = 0; g < GG; g++) { g_start[g] = s; s += g_ints[NN + g]; }
    }
}

__global__ void fill_kernel(const int* __restrict__ ei, int E) {
    int e = blockIdx.x * blockDim.x + threadIdx.x;
    if (e < E) {
        int dst = ei[E + e];
        int p = atomicAdd(&g_cursor[dst], 1);
        g_csr[p] = ei[e];
    }
}

// ---------------- xs0 = fp16(dis * x), x is [N,128] fp32 ----------------
__global__ void conv_x0_kernel(const float* __restrict__ x, int n) {
    int i = blockIdx.x * blockDim.x + threadIdx.x;  // over n*64 half2
    if (i >= n * 64) return;
    int node = i >> 6;
    float d = g_dis[node];
    float2 a = reinterpret_cast<const float2*>(x)[i];
    reinterpret_cast<__half2*>(g_xs16)[i] = __floats2half2_rn(d * a.x, d * a.y);
}

// All 4 W's -> transposed fp16 hi/lo splits, one launch.
__global__ void conv_w_all(const float* __restrict__ W0, const float* __restrict__ W1,
                           const float* __restrict__ W2, const float* __restrict__ W3) {
    int i = blockIdx.x * blockDim.x + threadIdx.x;
    if (i >= 32768 + 3 * 65536) return;
    const float* W;
    int layer, KD, idx;
    if (i < 32768) { W = W0; layer = 0; KD = 128; idx = i; }
    else {
        int j = i - 32768;
        layer = 1 + j / 65536;
        idx = j % 65536;
        W = (layer == 1) ? W1 : (layer == 2 ? W2 : W3);
        KD = 256;
    }
    int k = idx >> 8;
    int n = idx & 255;
    float w = W[idx];
    __half h = __float2half_rn(w);
    size_t off = (size_t)layer * DD * DD + (size_t)n * KD + k;
    g_Wth[off] = h;
    g_Wtl[off] = __float2half_rn(w - __half2float(h));
}

// ---------------- CSR aggregate (fp16 gather, fp32 accum) --------------------
template<int KD>
__global__ void __launch_bounds__(256) aggregate_kernel(int n) {
    int node = blockIdx.x * 4 + (threadIdx.x >> 6);
    int f    = threadIdx.x & 63;
    if (node >= n) return;

    int s = g_rowstart[node];
    int e = g_rowend[node];
    const char* xs = (const char*)g_xs16;
    constexpr size_t ROWB = KD * 2;

    if constexpr (KD == 256) {
        uint2 sv = __ldg((const uint2*)(xs + (size_t)node * ROWB) + f);
        float2 a0 = __half22float2(*(__half2*)&sv.x);
        float2 a1 = __half22float2(*(__half2*)&sv.y);
        int i = s;
        for (; i + 4 <= e; i += 4) {
            int s0 = __ldg(&g_csr[i]);
            int s1 = __ldg(&g_csr[i + 1]);
            int s2 = __ldg(&g_csr[i + 2]);
            int s3 = __ldg(&g_csr[i + 3]);
            uint2 v0 = __ldg((const uint2*)(xs + (size_t)s0 * ROWB) + f);
            uint2 v1 = __ldg((const uint2*)(xs + (size_t)s1 * ROWB) + f);
            uint2 v2 = __ldg((const uint2*)(xs + (size_t)s2 * ROWB) + f);
            uint2 v3 = __ldg((const uint2*)(xs + (size_t)s3 * ROWB) + f);
            float2 t;
            t = __half22float2(*(__half2*)&v0.x); a0.x += t.x; a0.y += t.y;
            t = __half22float2(*(__half2*)&v0.y); a1.x += t.x; a1.y += t.y;
            t = __half22float2(*(__half2*)&v1.x); a0.x += t.x; a0.y += t.y;
            t = __half22float2(*(__half2*)&v1.y); a1.x += t.x; a1.y += t.y;
            t = __half22float2(*(__half2*)&v2.x); a0.x += t.x; a0.y += t.y;
            t = __half22float2(*(__half2*)&v2.y); a1.x += t.x; a1.y += t.y;
            t = __half22float2(*(__half2*)&v3.x); a0.x += t.x; a0.y += t.y;
            t = __half22float2(*(__half2*)&v3.y); a1.x += t.x; a1.y += t.y;
        }
        for (; i < e; i++) {
            int s0 = __ldg(&g_csr[i]);
            uint2 v = __ldg((const uint2*)(xs + (size_t)s0 * ROWB) + f);
            float2 t;
            t = __half22float2(*(__half2*)&v.x); a0.x += t.x; a0.y += t.y;
            t = __half22float2(*(__half2*)&v.y); a1.x += t.x; a1.y += t.y;
        }
        float d = g_dis[node];
        __half2 y0 = __floats2half2_rn(d * a0.x, d * a0.y);
        __half2 y1 = __floats2half2_rn(d * a1.x, d * a1.y);
        reinterpret_cast<uint2*>(g_Y16)[(size_t)node * 64 + f] =
            make_uint2(*reinterpret_cast<uint32_t*>(&y0),
                       *reinterpret_cast<uint32_t*>(&y1));
    } else {  // KD == 128
        uint32_t sv = __ldg((const uint32_t*)(xs + (size_t)node * ROWB) + f);
        float2 a0 = __half22float2(*(__half2*)&sv);
        int i = s;
        for (; i + 4 <= e; i += 4) {
            int s0 = __ldg(&g_csr[i]);
            int s1 = __ldg(&g_csr[i + 1]);
            int s2 = __ldg(&g_csr[i + 2]);
            int s3 = __ldg(&g_csr[i + 3]);
            uint32_t v0 = __ldg((const uint32_t*)(xs + (size_t)s0 * ROWB) + f);
            uint32_t v1 = __ldg((const uint32_t*)(xs + (size_t)s1 * ROWB) + f);
            uint32_t v2 = __ldg((const uint32_t*)(xs + (size_t)s2 * ROWB) + f);
            uint32_t v3 = __ldg((const uint32_t*)(xs + (size_t)s3 * ROWB) + f);
            float2 t;
            t = __half22float2(*(__half2*)&v0); a0.x += t.x; a0.y += t.y;
            t = __half22float2(*(__half2*)&v1); a0.x += t.x; a0.y += t.y;
            t = __half22float2(*(__half2*)&v2); a0.x += t.x; a0.y += t.y;
            t = __half22float2(*(__half2*)&v3); a0.x += t.x; a0.y += t.y;
        }
        for (; i < e; i++) {
            int s0 = __ldg(&g_csr[i]);
            uint32_t v = __ldg((const uint32_t*)(xs + (size_t)s0 * ROWB) + f);
            float2 t = __half22float2(*(__half2*)&v);
            a0.x += t.x; a0.y += t.y;
        }
        float d = g_dis[node];
        __half2 y = __floats2half2_rn(d * a0.x, d * a0.y);
        reinterpret_cast<uint32_t*>(g_Y16)[(size_t)node * 64 + f] =
            *reinterpret_cast<uint32_t*>(&y);
    }
}

// ---------------- fp16 2-product GEMM (mma.sync + ldmatrix + 3-stage cp.async)
#define ARRB 4096               // 128 rows * 32B
#define STGB (3 * ARRB)         // 12288 (Y, Wh, Wl)
#define SM_TOTAL (3 * STGB)     // 36864

template<int KD, bool LAST>
__global__ void __launch_bounds__(256, 2) gemm_mma(const __half* __restrict__ Wh,
                                                   const __half* __restrict__ Wl,
                                                   const float* __restrict__ bias,
                                                   int M) {
    extern __shared__ char smc[];
    const uint32_t sb = smem_u32(smc);
    const int t    = threadIdx.x;
    const int lane = t & 31;
    const int w    = t >> 5;
    const int wm   = w & 3;
    const int wn   = w >> 2;
    const int m0   = blockIdx.y * 128;
    const int n0   = blockIdx.x * 128;

    float acc[2][8][4];
#pragma unroll
    for (int mt = 0; mt < 2; mt++)
#pragma unroll
        for (int nt = 0; nt < 8; nt++)
#pragma unroll
            for (int q = 0; q < 4; q++) acc[mt][nt][q] = 0.0f;

    auto stage = [&](int c, int buf) {
#pragma unroll
        for (int j = 0; j < 3; j++) {
            int idx = t + j * 256;
            int arr = idx >> 8;       // 0=Y 1=Wh 2=Wl
            int rem = idx & 255;
            int row = rem >> 1;
            int cc  = rem & 1;
            const __half* src;
            int gr;
            if (arr == 0)      { src = g_Y16; gr = m0 + row; }
            else if (arr == 1) { src = Wh;    gr = n0 + row; }
            else               { src = Wl;    gr = n0 + row; }
            src += (size_t)gr * KD + c * 16 + cc * 8;
            uint32_t dst = sb + buf * STGB + arr * ARRB + row * 32 +
                           ((cc ^ ((row >> 2) & 1)) << 4);
            cp16(dst, src);
        }
        CP_COMMIT();
    };

    stage(0, 0);
    stage(1, 1);

    const int NCH = KD / 16;
    const int lr  = lane & 7;
    const int grp = lane >> 3;

    for (int c = 0; c < NCH; c++) {
        asm volatile("cp.async.wait_group 1;" ::: "memory");
        __syncthreads();
        int buf = c % 3;
        uint32_t sA  = sb + buf * STGB;
        uint32_t sBh = sA + ARRB;
        uint32_t sBl = sA + 2 * ARRB;

        uint32_t af[2][4];
#pragma unroll
        for (int mt = 0; mt < 2; mt++) {
            int row = wm * 32 + mt * 16 + lr + ((grp & 1) << 3);
            int cc  = grp >> 1;
            uint32_t off = row * 32 + ((cc ^ ((row >> 2) & 1)) << 4);
            LDMX4(af[mt], sA + off);
        }

        if (c + 2 < NCH) stage(c + 2, (c + 2) % 3);

#pragma unroll
        for (int ntp = 0; ntp < 4; ntp++) {
            int row = wn * 64 + ntp * 16 + lr + ((grp >> 1) << 3);
            int cc  = grp & 1;
            uint32_t off = row * 32 + ((cc ^ ((row >> 2) & 1)) << 4);
            uint32_t bh[4], bl[4];
            LDMX4(bh, sBh + off);
            LDMX4(bl, sBl + off);
#pragma unroll
            for (int mt = 0; mt < 2; mt++) {
                MMA_FP16(acc[mt][2 * ntp],     af[mt], bh[0], bh[1]);
                MMA_FP16(acc[mt][2 * ntp],     af[mt], bl[0], bl[1]);
                MMA_FP16(acc[mt][2 * ntp + 1], af[mt], bh[2], bh[3]);
                MMA_FP16(acc[mt][2 * ntp + 1], af[mt], bl[2], bl[3]);
            }
        }
    }

    // epilogue
    float* actout = (float*)g_act4;
#pragma unroll
    for (int mt = 0; mt < 2; mt++) {
        int r0 = m0 + wm * 32 + mt * 16 + (lane >> 2);
        int r1 = r0 + 8;
        float d0 = (r0 < M) ? g_dis[r0] : 0.0f;
        float d1 = (r1 < M) ? g_dis[r1] : 0.0f;
#pragma unroll
        for (int nt = 0; nt < 8; nt++) {
            int nc = n0 + wn * 64 + nt * 8 + (lane & 3) * 2;
            float b0 = __ldg(&bias[nc]);
            float b1 = __ldg(&bias[nc + 1]);
            if (r0 < M) {
                float t0 = tanhf(acc[mt][nt][0] + b0);
                float t1 = tanhf(acc[mt][nt][1] + b1);
                if (LAST) {
                    *reinterpret_cast<float2*>(actout + (size_t)r0 * DD + nc) =
                        make_float2(t0, t1);
                } else {
                    *reinterpret_cast<__half2*>(g_xs16 + (size_t)r0 * DD + nc) =
                        __floats2half2_rn(d0 * t0, d0 * t1);
                }
            }
            if (r1 < M) {
                float t2 = tanhf(acc[mt][nt][2] + b0);
                float t3 = tanhf(acc[mt][nt][3] + b1);
                if (LAST) {
                    *reinterpret_cast<float2*>(actout + (size_t)r1 * DD + nc) =
                        make_float2(t2, t3);
                } else {
                    *reinterpret_cast<__half2*>(g_xs16 + (size_t)r1 * DD + nc) =
                        __floats2half2_rn(d1 * t2, d1 * t3);
                }
            }
        }
    }
}

// ---------------- per-graph max + mean pooling (64-feature strips) ----------
__global__ void pool_kernel() {
    int g  = blockIdx.x;
    int fc = blockIdx.y;
    int f  = fc * 64 + threadIdx.x;
    int s  = g_start[g];
    int c  = g_ints[NN + g];
    const float* act = (const float*)g_act4;
    float mx = -INFINITY, sm = 0.f;
    for (int r = 0; r < c; r++) {
        float v = act[(size_t)(s + r) * DD + f];
        mx = fmaxf(mx, v);
        sm += v;
    }
    g_pool[g * (2 * DD) + f]      = mx;
    g_pool[g * (2 * DD) + DD + f] = sm / fmaxf((float)c, 1.0f);
}

// ---------------- fused 3-layer MLP: one block per graph ----------------
__global__ void __launch_bounds__(256) mlp_fused(
    const float* __restrict__ fc1w, const float* __restrict__ fc1b,
    const float* __restrict__ fc2w, const float* __restrict__ fc2b,
    const float* __restrict__ ow,   const float* __restrict__ ob,
    float* __restrict__ out) {
    __shared__ float sA[512];
    __shared__ float sB[512];
    int row = blockIdx.x;
    int t = threadIdx.x;

    // load pooled features (512)
    for (int k = t; k < 512; k += 256) sA[k] = g_pool[row * 512 + k];
    __syncthreads();

    // fc1: 512 -> 512, relu
    for (int n = t; n < 512; n += 256) {
        float acc = fc1b[n];
        for (int k = 0; k < 512; k++) acc = fmaf(sA[k], fc1w[(size_t)k * 512 + n], acc);
        sB[n] = fmaxf(acc, 0.f);
    }
    __syncthreads();

    // fc2: 512 -> 256, relu
    for (int n = t; n < 256; n += 256) {
        float acc = fc2b[n];
        for (int k = 0; k < 512; k++) acc = fmaf(sB[k], fc2w[(size_t)k * 256 + n], acc);
        sA[n] = fmaxf(acc, 0.f);
    }
    __syncthreads();

    // out: 256 -> 10
    if (t < 10) {
        float acc = ob[t];
        for (int k = 0; k < 256; k++) acc = fmaf(sA[k], ow[(size_t)k * 10 + t], acc);
        out[(size_t)row * 10 + t] = acc;
    }
}

// ---------------- launch ----------------
extern "C" void kernel_launch(void* const* d_in, const int* in_sizes, int n_in,
                              void* d_out, int out_size) {
    const float* x   = (const float*)d_in[0];
    const int*   ei  = (const int*)d_in[1];
    const int*   bi  = (const int*)d_in[2];
    const float* W0 = (const float*)d_in[3];  const float* b0 = (const float*)d_in[4];
    const float* W1 = (const float*)d_in[5];  const float* b1 = (const float*)d_in[6];
    const float* W2 = (const float*)d_in[7];  const float* b2 = (const float*)d_in[8];
    const float* W3 = (const float*)d_in[9];  const float* b3 = (const float*)d_in[10];
    const float* fc1w = (const float*)d_in[11]; const float* fc1b = (const float*)d_in[12];
    const float* fc2w = (const float*)d_in[13]; const float* fc2b = (const float*)d_in[14];
    const float* ow   = (const float*)d_in[15]; const float* ob   = (const float*)d_in[16];

    const int F = 128;
    int N = in_sizes[0] / F;
    int E = in_sizes[1] / 2;
    int NB = (N + 255) / 256;

    static cudaStream_t s2 = nullptr;
    static cudaEvent_t evFork = nullptr, evAlloc = nullptr, evJoin = nullptr;
    if (!s2) {
        cudaStreamCreateWithFlags(&s2, cudaStreamNonBlocking);
        cudaEventCreateWithFlags(&evFork, cudaEventDisableTiming);
        cudaEventCreateWithFlags(&evAlloc, cudaEventDisableTiming);
        cudaEventCreateWithFlags(&evJoin, cudaEventDisableTiming);
    }

    void *p_ints, *p_wh, *p_wl;
    cudaGetSymbolAddress(&p_ints, g_ints);
    cudaGetSymbolAddress(&p_wh,   g_Wth);
    cudaGetSymbolAddress(&p_wl,   g_Wtl);

    dim3 ggrid(2, (N + 127) / 128);
    int ablocks = (N + 3) / 4;

    // ---- prep: fork side stream for independent work ----
    cudaEventRecord(evFork, 0);
    cudaStreamWaitEvent(s2, evFork, 0);

    // side stream: W splits (no deps)
    conv_w_all<<<(32768 + 3 * 65536 + 255) / 256, 256, 0, s2>>>(W0, W1, W2, W3);

    // main stream: degree/batch -> alloc -> fill
    cudaMemsetAsync(p_ints, 0, (size_t)(NN + GG) * sizeof(int), 0);
    deg_kernel<<<(E + 255) / 256, 256>>>(ei, bi, E, N);
    alloc_kernel<<<NB, 256>>>(N);
    cudaEventRecord(evAlloc, 0);
    fill_kernel<<<(E + 255) / 256, 256>>>(ei, E);

    // side stream: conv_x0 after alloc (needs dis), overlaps fill
    cudaStreamWaitEvent(s2, evAlloc, 0);
    conv_x0_kernel<<<(N * 64 + 255) / 256, 256, 0, s2>>>(x, N);
    cudaEventRecord(evJoin, s2);
    cudaStreamWaitEvent(0, evJoin, 0);

    const __half* wh = (const __half*)p_wh;
    const __half* wl = (const __half*)p_wl;

    aggregate_kernel<128><<<ablocks, 256>>>(N);
    gemm_mma<128, false><<<ggrid, 256, SM_TOTAL>>>(wh, wl, b0, N);

    aggregate_kernel<256><<<ablocks, 256>>>(N);
    gemm_mma<256, false><<<ggrid, 256, SM_TOTAL>>>(wh + DD * DD, wl + DD * DD, b1, N);

    aggregate_kernel<256><<<ablocks, 256>>>(N);
    gemm_mma<256, false><<<ggrid, 256, SM_TOTAL>>>(wh + 2 * DD * DD, wl + 2 * DD * DD, b2, N);

    aggregate_kernel<256><<<ablocks, 256>>>(N);
    gemm_mma<256, true><<<ggrid, 256, SM_TOTAL>>>(wh + 3 * DD * DD, wl + 3 * DD * DD, b3, N);

    // pooling + fused MLP
    pool_kernel<<<dim3(GG, 4), 64>>>();
    mlp_fused<<<GG, 256>>>(fc1w, fc1b, fc2w, fc2b, ow, ob, (float*)d_out);
}